// round 11
// baseline (speedup 1.0000x reference)
#include <cuda_runtime.h>
#include <cuda_fp16.h>
#include <cstdint>
#include <math.h>

#define BDIM 4
#define CH   128
#define C3   384
#define HH   128
#define WW   128
#define HW   (HH*WW)

__device__ __half g_x   [(size_t)BDIM * HH * WW * CH];  // x NHWC fp16
__device__ __half g_wp  [3 * 384 * 384];                // Weff [r][co][s*128+ci] fp16
__device__ __half g_wpj [128 * 128];                    // proj W fp16 (co,ci)
__device__ __half g_qkvh[(size_t)BDIM * C3 * HW];       // conv out (b,c,h,w) fp16
__device__ __half g_att [(size_t)BDIM * CH * HW];       // attn out (b,c,h,w) fp16

__device__ __forceinline__ uint32_t smem_to_u32(const void* p) {
    uint32_t a;
    asm("{ .reg .u64 t; cvta.to.shared.u64 t, %1; cvt.u32.u64 %0, t; }" : "=r"(a) : "l"(p));
    return a;
}
#define CP_ASYNC16(dst, src, sz) \
    asm volatile("cp.async.cg.shared.global [%0], [%1], 16, %2;" \
        :: "r"(dst), "l"(src), "r"(sz) : "memory")
#define CP_COMMIT() asm volatile("cp.async.commit_group;" ::: "memory")
#define CP_WAIT(n)  asm volatile("cp.async.wait_group %0;" :: "n"(n) : "memory")

#define LDSM_X4(r0, r1, r2, r3, addr) \
    asm volatile("ldmatrix.sync.aligned.m8n8.x4.shared.b16 {%0,%1,%2,%3}, [%4];" \
        : "=r"(r0), "=r"(r1), "=r"(r2), "=r"(r3) : "r"(addr))
#define LDSM_X4_T(r0, r1, r2, r3, addr) \
    asm volatile("ldmatrix.sync.aligned.m8n8.x4.trans.shared.b16 {%0,%1,%2,%3}, [%4];" \
        : "=r"(r0), "=r"(r1), "=r"(r2), "=r"(r3) : "r"(addr))

#define MMA16816(c, a, b0v, b1v) \
    asm volatile("mma.sync.aligned.m16n8k16.row.col.f32.f16.f16.f32 " \
        "{%0,%1,%2,%3}, {%4,%5,%6,%7}, {%8,%9}, {%0,%1,%2,%3};" \
        : "+f"((c)[0]), "+f"((c)[1]), "+f"((c)[2]), "+f"((c)[3]) \
        : "r"((a)[0]), "r"((a)[1]), "r"((a)[2]), "r"((a)[3]), "r"(b0v), "r"(b1v))

// ============ merged prep: xprep (blocks 0..511), weff (512..565), wpj (566)
__global__ __launch_bounds__(256) void prep_kernel(
    const float* __restrict__ X, const float* __restrict__ W1,
    const float* __restrict__ W2, const float* __restrict__ Wpj)
{
    extern __shared__ float smf[];
    const int blk = blockIdx.x;
    const int tid = threadIdx.x;

    if (blk < 512) {
        // ---- xprep: x NCHW fp32 -> NHWC fp16, smem [128ci][132]
        const int b = blk >> 7, h = blk & 127;
        const float* xb = X + ((size_t)b * CH) * HW + (size_t)h * WW;
        for (int i4 = tid; i4 < 128 * 32; i4 += 256) {
            int ci = i4 >> 5, w4 = (i4 & 31) << 2;
            *reinterpret_cast<float4*>(smf + ci * 132 + w4) =
                *reinterpret_cast<const float4*>(xb + (size_t)ci * HW + w4);
        }
        __syncthreads();
#pragma unroll
        for (int j = 0; j < 8; j++) {
            int unit = tid + j * 256;
            int w = unit >> 4, ci0 = (unit & 15) * 8;
            __half hb[8];
#pragma unroll
            for (int k = 0; k < 8; k++) hb[k] = __float2half(smf[(ci0 + k) * 132 + w]);
            *reinterpret_cast<uint4*>(g_x + ((size_t)(b * 128 + h) * 128 + w) * 128 + ci0) =
                *reinterpret_cast<uint4*>(hb);
        }
    } else if (blk < 566) {
        // ---- weff: Weff[co,ci;r,s] = sum_c W2[co,c,r,s] W1[c,ci]
        float* W1s = smf;                 // [64c][128ci]
        float* W2s = smf + 64 * 128;      // [64c][68]
        const int bb = blk - 512;
        const int rs = bb / 6, r = rs / 3, s = rs % 3;
        const int co0 = (bb % 6) * 64;
        const int tx = tid & 31, ty = tid >> 5;

        float acc[8][4];
#pragma unroll
        for (int j = 0; j < 8; j++)
#pragma unroll
            for (int m = 0; m < 4; m++) acc[j][m] = 0.f;

        for (int c0 = 0; c0 < 384; c0 += 64) {
            __syncthreads();
            for (int i4 = tid; i4 < 64 * 32; i4 += 256) {
                int c = i4 >> 5, ci4 = (i4 & 31) << 2;
                *reinterpret_cast<float4*>(W1s + c * 128 + ci4) =
                    *reinterpret_cast<const float4*>(W1 + (size_t)(c0 + c) * 128 + ci4);
            }
            for (int idx = tid; idx < 4096; idx += 256) {
                int co = idx & 63, c = idx >> 6;
                W2s[c * 68 + co] = W2[(size_t)(co0 + co) * 3456 + (c0 + c) * 9 + r * 3 + s];
            }
            __syncthreads();
#pragma unroll 2
            for (int c = 0; c < 64; c++) {
                float4 xv = *reinterpret_cast<const float4*>(W1s + c * 128 + tx * 4);
                const float* wr = W2s + c * 68 + ty * 8;
                float4 wa = *reinterpret_cast<const float4*>(wr);
                float4 wb = *reinterpret_cast<const float4*>(wr + 4);
                float wv[8] = {wa.x, wa.y, wa.z, wa.w, wb.x, wb.y, wb.z, wb.w};
#pragma unroll
                for (int j = 0; j < 8; j++) {
                    acc[j][0] += wv[j] * xv.x; acc[j][1] += wv[j] * xv.y;
                    acc[j][2] += wv[j] * xv.z; acc[j][3] += wv[j] * xv.w;
                }
            }
        }
#pragma unroll
        for (int j = 0; j < 8; j++) {
            __half hb[4];
#pragma unroll
            for (int m = 0; m < 4; m++) hb[m] = __float2half(acc[j][m]);
            int co = co0 + ty * 8 + j;
            *reinterpret_cast<uint2*>(g_wp + (size_t)(r * 384 + co) * 384 + s * 128 + tx * 4) =
                *reinterpret_cast<uint2*>(hb);
        }
    } else {
        // ---- wpjprep
        for (int i = tid; i < 16384; i += 256) g_wpj[i] = __float2half(Wpj[i]);
    }
}

// ======== conv3x3 via mma.sync fp16: CTA 128co x 256px (2 rows), warp 64x64
// K = 3r x 6 chunks of 64. Double buffer: 2 x (A 16KB + B 32KB) = 96KB. occ 1.
#define NCHUNK 18
__global__ __launch_bounds__(256, 1) void conv3x3_mma()
{
    extern __shared__ __align__(1024) char smem[];
    const uint32_t sb = smem_to_u32(smem);
    const int tid = threadIdx.x, wid = tid >> 5, lane = tid & 31;
    const int bx = blockIdx.x, b = bx >> 6, h0 = (bx & 63) * 2;
    const int co0 = blockIdx.y * 128;
    const int wm = wid & 1, wn = wid >> 1;        // 2(m) x 4(n)
    const int mwbase = wm * 64, nwbase = wn * 64; // warp tile 64co x 64px

    float acc[4][8][4];
#pragma unroll
    for (int i = 0; i < 4; i++)
#pragma unroll
        for (int j = 0; j < 8; j++)
#pragma unroll
            for (int k = 0; k < 4; k++) acc[i][j][k] = 0.f;

    auto stage = [&](int it, int buf) {
        const int r = it / 6, kc = it % 6;
        const uint32_t abase = sb + (uint32_t)buf * 49152u;
        const uint32_t bbase = abase + 16384u;
#pragma unroll
        for (int j = 0; j < 12; j++) {
            int idx = tid + j * 256;              // 0..3071
            if (idx < 1024) {
                int rw = idx >> 3, u = idx & 7;
                uint32_t dof = (uint32_t)(rw * 128 + ((u ^ (rw & 7)) << 4));
                const __half* src = g_wp +
                    ((size_t)(r * 384 + co0 + rw) * 384 + kc * 64 + u * 8);
                CP_ASYNC16(abase + dof, src, 16);
            } else {
                int v = idx - 1024;               // 0..2047
                int rw = v >> 3, u = v & 7;       // rw 0..255
                int p = rw >> 7, w = rw & 127;
                uint32_t dof = (uint32_t)(rw * 128 + ((u ^ (rw & 7)) << 4));
                int hr = h0 + p + r - 1;
                int L  = (w - 1) * 128 + kc * 64 + u * 8;
                bool ok = ((unsigned)hr < 128u) && ((unsigned)L < 16384u);
                const __half* src = g_x +
                    (ok ? ((size_t)(b * 128 + hr) * 16384 + L) : 0);
                CP_ASYNC16(bbase + dof, src, ok ? 16 : 0);
            }
        }
        CP_COMMIT();
    };

    stage(0, 0);
    for (int it = 0; it < NCHUNK; it++) {
        const int buf = it & 1;
        if (it + 1 < NCHUNK) { stage(it + 1, buf ^ 1); CP_WAIT(1); }
        else                 { CP_WAIT(0); }
        __syncthreads();

        const uint32_t abase = sb + (uint32_t)buf * 49152u;
        const uint32_t bbase = abase + 16384u;
        const int q4 = lane >> 3;
        const int qr = (q4 & 1) * 8 + (lane & 7);
        const int qk = q4 >> 1;
#pragma unroll
        for (int ks = 0; ks < 4; ks++) {
            const int u = ks * 2 + qk;
            uint32_t ah[4][4], bh[4][4];
#pragma unroll
            for (int mf = 0; mf < 4; mf++) {
                int rw = mwbase + mf * 16 + qr;
                LDSM_X4(ah[mf][0], ah[mf][1], ah[mf][2], ah[mf][3],
                        abase + (uint32_t)(rw * 128 + ((u ^ (rw & 7)) << 4)));
            }
#pragma unroll
            for (int g = 0; g < 4; g++) {
                int rw = nwbase + g * 16 + qr;
                LDSM_X4(bh[g][0], bh[g][1], bh[g][2], bh[g][3],
                        bbase + (uint32_t)(rw * 128 + ((u ^ (rw & 7)) << 4)));
            }
#pragma unroll
            for (int mf = 0; mf < 4; mf++)
#pragma unroll
                for (int nf = 0; nf < 8; nf++)
                    MMA16816(acc[mf][nf], ah[mf],
                             bh[nf >> 1][nf & 1], bh[nf >> 1][(nf & 1) + 2]);
        }
        __syncthreads();
    }

    // epilogue: warp covers co [co0+mwbase, +64) x px [nwbase, +64); p = wn>>1
    const int gid = lane >> 2, tg = lane & 3;
    const int p = wn >> 1, h = h0 + p;
    const int wbase = (nwbase & 127);
#pragma unroll
    for (int mf = 0; mf < 4; mf++) {
        int co = co0 + mwbase + mf * 16 + gid;
        __half* base0 = g_qkvh + (((size_t)b * C3 + co) * HH + h) * WW;
        __half* base1 = g_qkvh + (((size_t)b * C3 + co + 8) * HH + h) * WW;
#pragma unroll
        for (int nf = 0; nf < 8; nf++) {
            int w = wbase + nf * 8 + tg * 2;
            *reinterpret_cast<__half2*>(base0 + w) =
                __floats2half2_rn(acc[mf][nf][0], acc[mf][nf][1]);
            *reinterpret_cast<__half2*>(base1 + w) =
                __floats2half2_rn(acc[mf][nf][2], acc[mf][nf][3]);
        }
    }
}

// ---------------- fused attention per (b,c), cp.async staged, norms folded --
__global__ __launch_bounds__(256, 2) void attn_mma(const float* __restrict__ scale)
{
    extern __shared__ __align__(1024) char smem[];
    const uint32_t sb = smem_to_u32(smem);
    const uint32_t QS = 0, KS = 32768, VS = 65536, NV = 98304;
    float* ninv = reinterpret_cast<float*>(smem + NV);
    const int bc = blockIdx.x, b = bc >> 7, c = bc & 127;
    const int tid = threadIdx.x, lane = tid & 31, wp = tid >> 5;
    const unsigned FULL = 0xffffffffu;

    const __half* srcbase = g_qkvh + ((size_t)b * C3 + c) * HW;
#pragma unroll
    for (int j = 0; j < 24; j++) {
        int idx = tid + j * 256;
        int sec = idx >> 11;
        int rem = idx & 2047;
        int row = rem >> 4, u = rem & 15;
        const __half* src = srcbase + ((size_t)sec * 128) * HW + (size_t)row * WW + u * 8;
        uint32_t dst = sb + (uint32_t)sec * 32768u
                     + (uint32_t)(row * 256 + ((u ^ (row & 7)) << 4));
        CP_ASYNC16(dst, src, 16);
    }
    CP_COMMIT(); CP_WAIT(0);
    __syncthreads();

    {
        int which = tid >> 7, row = tid & 127;
        const char* base = smem + which * 32768 + row * 256;
        float ss = 0.f;
#pragma unroll
        for (int u = 0; u < 16; u++) {
            uint4 vv = *reinterpret_cast<const uint4*>(base + ((u ^ (row & 7)) << 4));
            float2 f;
            f = __half22float2(*reinterpret_cast<__half2*>(&vv.x)); ss += f.x * f.x + f.y * f.y;
            f = __half22float2(*reinterpret_cast<__half2*>(&vv.y)); ss += f.x * f.x + f.y * f.y;
            f = __half22float2(*reinterpret_cast<__half2*>(&vv.z)); ss += f.x * f.x + f.y * f.y;
            f = __half22float2(*reinterpret_cast<__half2*>(&vv.w)); ss += f.x * f.x + f.y * f.y;
        }
        ninv[which * 128 + row] = 1.0f / fmaxf(sqrtf(ss), 1e-12f);
    }
    __syncthreads();

    const int m0 = wp * 16;
    const int q4 = lane >> 3;
    const int qr = (q4 & 1) * 8 + (lane & 7);
    const int qk = q4 >> 1;

    float sacc[16][4];
#pragma unroll
    for (int nt = 0; nt < 16; nt++)
#pragma unroll
        for (int k = 0; k < 4; k++) sacc[nt][k] = 0.f;

#pragma unroll 1
    for (int ks = 0; ks < 8; ks++) {
        const int u = ks * 2 + qk;
        uint32_t a[4];
        int ar = m0 + qr;
        LDSM_X4(a[0], a[1], a[2], a[3],
                sb + QS + (uint32_t)(ar * 256 + ((u ^ (ar & 7)) << 4)));
#pragma unroll
        for (int nt2 = 0; nt2 < 8; nt2++) {
            uint32_t bb[4];
            int br = nt2 * 16 + qr;
            LDSM_X4(bb[0], bb[1], bb[2], bb[3],
                    sb + KS + (uint32_t)(br * 256 + ((u ^ (br & 7)) << 4)));
            MMA16816(sacc[2 * nt2],     a, bb[0], bb[2]);
            MMA16816(sacc[2 * nt2 + 1], a, bb[1], bb[3]);
        }
    }

    const float sc = __ldg(scale + c);
    const int r0 = m0 + (lane >> 2);
    const float qs0 = ninv[r0] * sc, qs1 = ninv[r0 + 8] * sc;
    float mx0 = -1e30f, mx1 = -1e30f;
#pragma unroll
    for (int nt = 0; nt < 16; nt++) {
        int cc = nt * 8 + (lane & 3) * 2;
        float k0 = ninv[128 + cc], k1 = ninv[128 + cc + 1];
        sacc[nt][0] *= qs0 * k0; sacc[nt][1] *= qs0 * k1;
        sacc[nt][2] *= qs1 * k0; sacc[nt][3] *= qs1 * k1;
        mx0 = fmaxf(mx0, fmaxf(sacc[nt][0], sacc[nt][1]));
        mx1 = fmaxf(mx1, fmaxf(sacc[nt][2], sacc[nt][3]));
    }
    mx0 = fmaxf(mx0, __shfl_xor_sync(FULL, mx0, 1));
    mx0 = fmaxf(mx0, __shfl_xor_sync(FULL, mx0, 2));
    mx1 = fmaxf(mx1, __shfl_xor_sync(FULL, mx1, 1));
    mx1 = fmaxf(mx1, __shfl_xor_sync(FULL, mx1, 2));
    float sum0 = 0.f, sum1 = 0.f;
#pragma unroll
    for (int nt = 0; nt < 16; nt++) {
        sacc[nt][0] = __expf(sacc[nt][0] - mx0);
        sacc[nt][1] = __expf(sacc[nt][1] - mx0);
        sacc[nt][2] = __expf(sacc[nt][2] - mx1);
        sacc[nt][3] = __expf(sacc[nt][3] - mx1);
        sum0 += sacc[nt][0] + sacc[nt][1];
        sum1 += sacc[nt][2] + sacc[nt][3];
    }
    sum0 += __shfl_xor_sync(FULL, sum0, 1); sum0 += __shfl_xor_sync(FULL, sum0, 2);
    sum1 += __shfl_xor_sync(FULL, sum1, 1); sum1 += __shfl_xor_sync(FULL, sum1, 2);
    const float inv0 = 1.0f / sum0, inv1 = 1.0f / sum1;

    uint32_t pf[8][4];
#pragma unroll
    for (int ks = 0; ks < 8; ks++) {
        __half2 t;
        t = __floats2half2_rn(sacc[2 * ks][0],     sacc[2 * ks][1]);     pf[ks][0] = *(uint32_t*)&t;
        t = __floats2half2_rn(sacc[2 * ks][2],     sacc[2 * ks][3]);     pf[ks][1] = *(uint32_t*)&t;
        t = __floats2half2_rn(sacc[2 * ks + 1][0], sacc[2 * ks + 1][1]); pf[ks][2] = *(uint32_t*)&t;
        t = __floats2half2_rn(sacc[2 * ks + 1][2], sacc[2 * ks + 1][3]); pf[ks][3] = *(uint32_t*)&t;
    }

    float oacc[16][4];
#pragma unroll
    for (int nt = 0; nt < 16; nt++)
#pragma unroll
        for (int k = 0; k < 4; k++) oacc[nt][k] = 0.f;

#pragma unroll 1
    for (int ks = 0; ks < 8; ks++) {
        const int vrow = ks * 16 + (lane & 15);
#pragma unroll
        for (int ntw = 0; ntw < 8; ntw++) {
            const int wu = ntw * 2 + (lane >> 4);
            uint32_t vv0, vv1, vv2, vv3;
            LDSM_X4_T(vv0, vv1, vv2, vv3,
                      sb + VS + (uint32_t)(vrow * 256 + ((wu ^ (vrow & 7)) << 4)));
            MMA16816(oacc[2 * ntw],     pf[ks], vv0, vv1);
            MMA16816(oacc[2 * ntw + 1], pf[ks], vv2, vv3);
        }
    }

    const int wq = 2 * (lane & 3);
    __half* ob0 = g_att + (((size_t)b * CH + c) * HH + r0) * WW;
    __half* ob1 = g_att + (((size_t)b * CH + c) * HH + r0 + 8) * WW;
#pragma unroll
    for (int nt = 0; nt < 16; nt++) {
        int w = nt * 8 + wq;
        *reinterpret_cast<__half2*>(ob0 + w) =
            __floats2half2_rn(oacc[nt][0] * inv0, oacc[nt][1] * inv0);
        *reinterpret_cast<__half2*>(ob1 + w) =
            __floats2half2_rn(oacc[nt][2] * inv1, oacc[nt][3] * inv1);
    }
}

// ---------------- proj 1x1 via fp16 mma: CTA per (b,h) row ----------------
__global__ __launch_bounds__(256, 2) void proj_mma(float* __restrict__ Y)
{
    extern __shared__ __align__(1024) char smem[];
    const uint32_t sb = smem_to_u32(smem);
    const uint32_t WS = 0, XS = 32768;
    const int bx = blockIdx.x, b = bx >> 7, h = bx & 127;
    const int tid = threadIdx.x, wid = tid >> 5, lane = tid & 31;
    const int wm = wid & 1, wn = wid >> 1;
    const int mwbase = wm * 64, nwbase = wn * 32;

#pragma unroll
    for (int j = 0; j < 16; j++) {
        int idx = tid + j * 256;
        int sec = idx >> 11;
        int rem = idx & 2047;
        int row = rem >> 4, u = rem & 15;
        const __half* src = sec
            ? (g_att + (((size_t)b * CH + row) * HH + h) * WW + u * 8)
            : (g_wpj + (size_t)row * 128 + u * 8);
        uint32_t dst = sb + (uint32_t)sec * 32768u
                     + (uint32_t)(row * 256 + ((u ^ (row & 7)) << 4));
        CP_ASYNC16(dst, src, 16);
    }
    CP_COMMIT(); CP_WAIT(0);
    __syncthreads();

    float acc[4][4][4];
#pragma unroll
    for (int i = 0; i < 4; i++)
#pragma unroll
        for (int j = 0; j < 4; j++)
#pragma unroll
            for (int k = 0; k < 4; k++) acc[i][j][k] = 0.f;

    const int q4 = lane >> 3;
    const int qr = (q4 & 1) * 8 + (lane & 7);
    const int qk = q4 >> 1;
#pragma unroll 1
    for (int ks = 0; ks < 8; ks++) {
        const int u = ks * 2 + qk;
        uint32_t ah[4][4];
#pragma unroll
        for (int mf = 0; mf < 4; mf++) {
            int rw = mwbase + mf * 16 + qr;
            LDSM_X4(ah[mf][0], ah[mf][1], ah[mf][2], ah[mf][3],
                    sb + WS + (uint32_t)(rw * 256 + ((u ^ (rw & 7)) << 4)));
        }
        const int vrow = ks * 16 + (lane & 15);
#pragma unroll
        for (int ntw = 0; ntw < 2; ntw++) {
            const int wu = (nwbase >> 3) + ntw * 2 + (lane >> 4);
            uint32_t vv0, vv1, vv2, vv3;
            LDSM_X4_T(vv0, vv1, vv2, vv3,
                      sb + XS + (uint32_t)(vrow * 256 + ((wu ^ (vrow & 7)) << 4)));
#pragma unroll
            for (int mf = 0; mf < 4; mf++) {
                MMA16816(acc[mf][ntw * 2],     ah[mf], vv0, vv1);
                MMA16816(acc[mf][ntw * 2 + 1], ah[mf], vv2, vv3);
            }
        }
    }

    const int gid = lane >> 2, tg = lane & 3;
#pragma unroll
    for (int mf = 0; mf < 4; mf++) {
        int co = mwbase + mf * 16 + gid;
        float* o0 = Y + (((size_t)b * CH + co) * HH + h) * WW;
        float* o1 = Y + (((size_t)b * CH + co + 8) * HH + h) * WW;
#pragma unroll
        for (int nf = 0; nf < 4; nf++) {
            int w = nwbase + nf * 8 + tg * 2;
            *reinterpret_cast<float2*>(o0 + w) = make_float2(acc[mf][nf][0], acc[mf][nf][1]);
            *reinterpret_cast<float2*>(o1 + w) = make_float2(acc[mf][nf][2], acc[mf][nf][3]);
        }
    }
}

// ---------------- launch ----------------
extern "C" void kernel_launch(void* const* d_in, const int* in_sizes, int n_in,
                              void* d_out, int out_size)
{
    (void)in_sizes; (void)n_in; (void)out_size;
    const float* x     = (const float*)d_in[0];
    const float* w1    = (const float*)d_in[1];
    const float* w2    = (const float*)d_in[2];
    const float* wproj = (const float*)d_in[3];
    const float* scale = (const float*)d_in[4];
    float* out = (float*)d_out;

    const int SMEM_PREP = 128 * 132 * 4;                //  67,584
    const int SMEM_CONV = 2 * 49152;                    //  98,304
    const int SMEM_ATTN = 3 * 32768 + 1024;             //  99,328
    const int SMEM_PROJ = 2 * 32768;                    //  65,536

    cudaFuncSetAttribute(prep_kernel, cudaFuncAttributeMaxDynamicSharedMemorySize, SMEM_PREP);
    cudaFuncSetAttribute(conv3x3_mma, cudaFuncAttributeMaxDynamicSharedMemorySize, SMEM_CONV);
    cudaFuncSetAttribute(attn_mma,    cudaFuncAttributeMaxDynamicSharedMemorySize, SMEM_ATTN);
    cudaFuncSetAttribute(proj_mma,    cudaFuncAttributeMaxDynamicSharedMemorySize, SMEM_PROJ);

    prep_kernel<<<567, 256, SMEM_PREP>>>(x, w1, w2, wproj);
    conv3x3_mma<<<dim3(BDIM * 64, C3 / 128), 256, SMEM_CONV>>>();
    attn_mma<<<BDIM * CH, 256, SMEM_ATTN>>>(scale);
    proj_mma<<<BDIM * HH, 256, SMEM_PROJ>>>(out);
}

// round 12
// speedup vs baseline: 1.1097x; 1.1097x over previous
#include <cuda_runtime.h>
#include <cuda_fp16.h>
#include <cstdint>
#include <math.h>

#define BDIM 4
#define CH   128
#define C3   384
#define HH   128
#define WW   128
#define HW   (HH*WW)

__device__ __half g_x   [(size_t)BDIM * HH * WW * CH];  // x NHWC fp16
__device__ __half g_wp  [3 * 384 * 384];                // Weff [r][co][s*128+ci] fp16
__device__ __half g_wpj [128 * 128];                    // proj W fp16 (co,ci)
__device__ __half g_qkvh[(size_t)BDIM * C3 * HW];       // conv out (b,c,h,w) fp16
__device__ __half g_att [(size_t)BDIM * CH * HW];       // attn out (b,c,h,w) fp16

__device__ __forceinline__ uint32_t smem_to_u32(const void* p) {
    uint32_t a;
    asm("{ .reg .u64 t; cvta.to.shared.u64 t, %1; cvt.u32.u64 %0, t; }" : "=r"(a) : "l"(p));
    return a;
}
#define CP_ASYNC16(dst, src, sz) \
    asm volatile("cp.async.cg.shared.global [%0], [%1], 16, %2;" \
        :: "r"(dst), "l"(src), "r"(sz) : "memory")
#define CP_COMMIT() asm volatile("cp.async.commit_group;" ::: "memory")
#define CP_WAIT(n)  asm volatile("cp.async.wait_group %0;" :: "n"(n) : "memory")

#define LDSM_X4(r0, r1, r2, r3, addr) \
    asm volatile("ldmatrix.sync.aligned.m8n8.x4.shared.b16 {%0,%1,%2,%3}, [%4];" \
        : "=r"(r0), "=r"(r1), "=r"(r2), "=r"(r3) : "r"(addr))
#define LDSM_X4_T(r0, r1, r2, r3, addr) \
    asm volatile("ldmatrix.sync.aligned.m8n8.x4.trans.shared.b16 {%0,%1,%2,%3}, [%4];" \
        : "=r"(r0), "=r"(r1), "=r"(r2), "=r"(r3) : "r"(addr))

#define MMA16816(c, a, b0v, b1v) \
    asm volatile("mma.sync.aligned.m16n8k16.row.col.f32.f16.f16.f32 " \
        "{%0,%1,%2,%3}, {%4,%5,%6,%7}, {%8,%9}, {%0,%1,%2,%3};" \
        : "+f"((c)[0]), "+f"((c)[1]), "+f"((c)[2]), "+f"((c)[3]) \
        : "r"((a)[0]), "r"((a)[1]), "r"((a)[2]), "r"((a)[3]), "r"(b0v), "r"(b1v))

// ============ merged prep: xprep (blocks 0..511), weff (512..565), wpj (566)
__global__ __launch_bounds__(256) void prep_kernel(
    const float* __restrict__ X, const float* __restrict__ W1,
    const float* __restrict__ W2, const float* __restrict__ Wpj)
{
    extern __shared__ float smf[];
    const int blk = blockIdx.x;
    const int tid = threadIdx.x;

    if (blk < 512) {
        // ---- xprep: x NCHW fp32 -> NHWC fp16, smem [128ci][132]
        const int b = blk >> 7, h = blk & 127;
        const float* xb = X + ((size_t)b * CH) * HW + (size_t)h * WW;
        for (int i4 = tid; i4 < 128 * 32; i4 += 256) {
            int ci = i4 >> 5, w4 = (i4 & 31) << 2;
            *reinterpret_cast<float4*>(smf + ci * 132 + w4) =
                *reinterpret_cast<const float4*>(xb + (size_t)ci * HW + w4);
        }
        __syncthreads();
#pragma unroll
        for (int j = 0; j < 8; j++) {
            int unit = tid + j * 256;
            int w = unit >> 4, ci0 = (unit & 15) * 8;
            __half hb[8];
#pragma unroll
            for (int k = 0; k < 8; k++) hb[k] = __float2half(smf[(ci0 + k) * 132 + w]);
            *reinterpret_cast<uint4*>(g_x + ((size_t)(b * 128 + h) * 128 + w) * 128 + ci0) =
                *reinterpret_cast<uint4*>(hb);
        }
    } else if (blk < 566) {
        // ---- weff: Weff[co,ci;r,s] = sum_c W2[co,c,r,s] W1[c,ci]
        float* W1s = smf;                 // [64c][128ci]
        float* W2s = smf + 64 * 128;      // [64c][68]
        const int bb = blk - 512;
        const int rs = bb / 6, r = rs / 3, s = rs % 3;
        const int co0 = (bb % 6) * 64;
        const int tx = tid & 31, ty = tid >> 5;

        float acc[8][4];
#pragma unroll
        for (int j = 0; j < 8; j++)
#pragma unroll
            for (int m = 0; m < 4; m++) acc[j][m] = 0.f;

        for (int c0 = 0; c0 < 384; c0 += 64) {
            __syncthreads();
            for (int i4 = tid; i4 < 64 * 32; i4 += 256) {
                int c = i4 >> 5, ci4 = (i4 & 31) << 2;
                *reinterpret_cast<float4*>(W1s + c * 128 + ci4) =
                    *reinterpret_cast<const float4*>(W1 + (size_t)(c0 + c) * 128 + ci4);
            }
            for (int idx = tid; idx < 4096; idx += 256) {
                int co = idx & 63, c = idx >> 6;
                W2s[c * 68 + co] = W2[(size_t)(co0 + co) * 3456 + (c0 + c) * 9 + r * 3 + s];
            }
            __syncthreads();
#pragma unroll 2
            for (int c = 0; c < 64; c++) {
                float4 xv = *reinterpret_cast<const float4*>(W1s + c * 128 + tx * 4);
                const float* wr = W2s + c * 68 + ty * 8;
                float4 wa = *reinterpret_cast<const float4*>(wr);
                float4 wb = *reinterpret_cast<const float4*>(wr + 4);
                float wv[8] = {wa.x, wa.y, wa.z, wa.w, wb.x, wb.y, wb.z, wb.w};
#pragma unroll
                for (int j = 0; j < 8; j++) {
                    acc[j][0] += wv[j] * xv.x; acc[j][1] += wv[j] * xv.y;
                    acc[j][2] += wv[j] * xv.z; acc[j][3] += wv[j] * xv.w;
                }
            }
        }
#pragma unroll
        for (int j = 0; j < 8; j++) {
            __half hb[4];
#pragma unroll
            for (int m = 0; m < 4; m++) hb[m] = __float2half(acc[j][m]);
            int co = co0 + ty * 8 + j;
            *reinterpret_cast<uint2*>(g_wp + (size_t)(r * 384 + co) * 384 + s * 128 + tx * 4) =
                *reinterpret_cast<uint2*>(hb);
        }
    } else {
        // ---- wpjprep
        for (int i = tid; i < 16384; i += 256) g_wpj[i] = __float2half(Wpj[i]);
    }
}

// ======== conv3x3 via mma.sync fp16 (R7 config: CTA 128co x 128px, warp 64x32,
// double buffer 2 x 32KB, occ 2). K = 3r x 6 chunks of 64.
#define NCHUNK 18
__global__ __launch_bounds__(256, 2) void conv3x3_mma()
{
    extern __shared__ __align__(1024) char smem[];
    const uint32_t sb = smem_to_u32(smem);
    const int tid = threadIdx.x, wid = tid >> 5, lane = tid & 31;
    const int bx = blockIdx.x, b = bx >> 7, h = bx & 127;
    const int co0 = blockIdx.y * 128;
    const int wm = wid & 1, wn = wid >> 1;
    const int mwbase = wm * 64, nwbase = wn * 32;

    float acc[4][4][4];
#pragma unroll
    for (int i = 0; i < 4; i++)
#pragma unroll
        for (int j = 0; j < 4; j++)
#pragma unroll
            for (int k = 0; k < 4; k++) acc[i][j][k] = 0.f;

    auto stage = [&](int it, int buf) {
        const int r = it / 6, kc = it % 6;
        const uint32_t abase = sb + (uint32_t)buf * 32768u;
        const uint32_t bbase = abase + 16384u;
#pragma unroll
        for (int j = 0; j < 8; j++) {
            int idx = tid + j * 256;
            int rw  = (idx >> 3) & 127;
            int u   = idx & 7;
            uint32_t dof = (uint32_t)(rw * 128 + ((u ^ (rw & 7)) << 4));
            if (idx < 1024) {
                const __half* src = g_wp +
                    ((size_t)(r * 384 + co0 + rw) * 384 + kc * 64 + u * 8);
                CP_ASYNC16(abase + dof, src, 16);
            } else {
                int hr = h + r - 1;
                int L  = (rw - 1) * 128 + kc * 64 + u * 8;
                bool ok = ((unsigned)hr < 128u) && ((unsigned)L < 16384u);
                const __half* src = g_x +
                    (ok ? ((size_t)(b * 128 + hr) * 16384 + L) : 0);
                CP_ASYNC16(bbase + dof, src, ok ? 16 : 0);
            }
        }
        CP_COMMIT();
    };

    stage(0, 0);
    for (int it = 0; it < NCHUNK; it++) {
        const int buf = it & 1;
        if (it + 1 < NCHUNK) { stage(it + 1, buf ^ 1); CP_WAIT(1); }
        else                 { CP_WAIT(0); }
        __syncthreads();

        const uint32_t abase = sb + (uint32_t)buf * 32768u;
        const uint32_t bbase = abase + 16384u;
        const int q4 = lane >> 3;
        const int qr = (q4 & 1) * 8 + (lane & 7);
        const int qk = q4 >> 1;
#pragma unroll
        for (int ks = 0; ks < 4; ks++) {
            const int u = ks * 2 + qk;
            uint32_t ah[4][4], bh[2][4];
#pragma unroll
            for (int mf = 0; mf < 4; mf++) {
                int rw = mwbase + mf * 16 + qr;
                LDSM_X4(ah[mf][0], ah[mf][1], ah[mf][2], ah[mf][3],
                        abase + (uint32_t)(rw * 128 + ((u ^ (rw & 7)) << 4)));
            }
#pragma unroll
            for (int g = 0; g < 2; g++) {
                int rw = nwbase + g * 16 + qr;
                LDSM_X4(bh[g][0], bh[g][1], bh[g][2], bh[g][3],
                        bbase + (uint32_t)(rw * 128 + ((u ^ (rw & 7)) << 4)));
            }
#pragma unroll
            for (int mf = 0; mf < 4; mf++)
#pragma unroll
                for (int nf = 0; nf < 4; nf++)
                    MMA16816(acc[mf][nf], ah[mf],
                             bh[nf >> 1][nf & 1], bh[nf >> 1][(nf & 1) + 2]);
        }
        __syncthreads();
    }

    const int gid = lane >> 2, tg = lane & 3;
#pragma unroll
    for (int mf = 0; mf < 4; mf++) {
        int co = co0 + mwbase + mf * 16 + gid;
        __half* base0 = g_qkvh + (((size_t)b * C3 + co) * HH + h) * WW;
        __half* base1 = g_qkvh + (((size_t)b * C3 + co + 8) * HH + h) * WW;
#pragma unroll
        for (int nf = 0; nf < 4; nf++) {
            int w = nwbase + nf * 8 + tg * 2;
            *reinterpret_cast<__half2*>(base0 + w) =
                __floats2half2_rn(acc[mf][nf][0], acc[mf][nf][1]);
            *reinterpret_cast<__half2*>(base1 + w) =
                __floats2half2_rn(acc[mf][nf][2], acc[mf][nf][3]);
        }
    }
}

// ---------------- fused attention per (b,c), cp.async staged, norms folded --
__global__ __launch_bounds__(256, 2) void attn_mma(const float* __restrict__ scale)
{
    extern __shared__ __align__(1024) char smem[];
    const uint32_t sb = smem_to_u32(smem);
    const uint32_t QS = 0, KS = 32768, VS = 65536, NV = 98304;
    float* ninv = reinterpret_cast<float*>(smem + NV);
    const int bc = blockIdx.x, b = bc >> 7, c = bc & 127;
    const int tid = threadIdx.x, lane = tid & 31, wp = tid >> 5;
    const unsigned FULL = 0xffffffffu;

    const __half* srcbase = g_qkvh + ((size_t)b * C3 + c) * HW;
#pragma unroll
    for (int j = 0; j < 24; j++) {
        int idx = tid + j * 256;
        int sec = idx >> 11;
        int rem = idx & 2047;
        int row = rem >> 4, u = rem & 15;
        const __half* src = srcbase + ((size_t)sec * 128) * HW + (size_t)row * WW + u * 8;
        uint32_t dst = sb + (uint32_t)sec * 32768u
                     + (uint32_t)(row * 256 + ((u ^ (row & 7)) << 4));
        CP_ASYNC16(dst, src, 16);
    }
    CP_COMMIT(); CP_WAIT(0);
    __syncthreads();

    {
        int which = tid >> 7, row = tid & 127;
        const char* base = smem + which * 32768 + row * 256;
        float ss = 0.f;
#pragma unroll
        for (int u = 0; u < 16; u++) {
            uint4 vv = *reinterpret_cast<const uint4*>(base + ((u ^ (row & 7)) << 4));
            float2 f;
            f = __half22float2(*reinterpret_cast<__half2*>(&vv.x)); ss += f.x * f.x + f.y * f.y;
            f = __half22float2(*reinterpret_cast<__half2*>(&vv.y)); ss += f.x * f.x + f.y * f.y;
            f = __half22float2(*reinterpret_cast<__half2*>(&vv.z)); ss += f.x * f.x + f.y * f.y;
            f = __half22float2(*reinterpret_cast<__half2*>(&vv.w)); ss += f.x * f.x + f.y * f.y;
        }
        ninv[which * 128 + row] = 1.0f / fmaxf(sqrtf(ss), 1e-12f);
    }
    __syncthreads();

    const int m0 = wp * 16;
    const int q4 = lane >> 3;
    const int qr = (q4 & 1) * 8 + (lane & 7);
    const int qk = q4 >> 1;

    float sacc[16][4];
#pragma unroll
    for (int nt = 0; nt < 16; nt++)
#pragma unroll
        for (int k = 0; k < 4; k++) sacc[nt][k] = 0.f;

#pragma unroll 1
    for (int ks = 0; ks < 8; ks++) {
        const int u = ks * 2 + qk;
        uint32_t a[4];
        int ar = m0 + qr;
        LDSM_X4(a[0], a[1], a[2], a[3],
                sb + QS + (uint32_t)(ar * 256 + ((u ^ (ar & 7)) << 4)));
#pragma unroll
        for (int nt2 = 0; nt2 < 8; nt2++) {
            uint32_t bb[4];
            int br = nt2 * 16 + qr;
            LDSM_X4(bb[0], bb[1], bb[2], bb[3],
                    sb + KS + (uint32_t)(br * 256 + ((u ^ (br & 7)) << 4)));
            MMA16816(sacc[2 * nt2],     a, bb[0], bb[2]);
            MMA16816(sacc[2 * nt2 + 1], a, bb[1], bb[3]);
        }
    }

    const float sc = __ldg(scale + c);
    const int r0 = m0 + (lane >> 2);
    const float qs0 = ninv[r0] * sc, qs1 = ninv[r0 + 8] * sc;
    float mx0 = -1e30f, mx1 = -1e30f;
#pragma unroll
    for (int nt = 0; nt < 16; nt++) {
        int cc = nt * 8 + (lane & 3) * 2;
        float k0 = ninv[128 + cc], k1 = ninv[128 + cc + 1];
        sacc[nt][0] *= qs0 * k0; sacc[nt][1] *= qs0 * k1;
        sacc[nt][2] *= qs1 * k0; sacc[nt][3] *= qs1 * k1;
        mx0 = fmaxf(mx0, fmaxf(sacc[nt][0], sacc[nt][1]));
        mx1 = fmaxf(mx1, fmaxf(sacc[nt][2], sacc[nt][3]));
    }
    mx0 = fmaxf(mx0, __shfl_xor_sync(FULL, mx0, 1));
    mx0 = fmaxf(mx0, __shfl_xor_sync(FULL, mx0, 2));
    mx1 = fmaxf(mx1, __shfl_xor_sync(FULL, mx1, 1));
    mx1 = fmaxf(mx1, __shfl_xor_sync(FULL, mx1, 2));
    float sum0 = 0.f, sum1 = 0.f;
#pragma unroll
    for (int nt = 0; nt < 16; nt++) {
        sacc[nt][0] = __expf(sacc[nt][0] - mx0);
        sacc[nt][1] = __expf(sacc[nt][1] - mx0);
        sacc[nt][2] = __expf(sacc[nt][2] - mx1);
        sacc[nt][3] = __expf(sacc[nt][3] - mx1);
        sum0 += sacc[nt][0] + sacc[nt][1];
        sum1 += sacc[nt][2] + sacc[nt][3];
    }
    sum0 += __shfl_xor_sync(FULL, sum0, 1); sum0 += __shfl_xor_sync(FULL, sum0, 2);
    sum1 += __shfl_xor_sync(FULL, sum1, 1); sum1 += __shfl_xor_sync(FULL, sum1, 2);
    const float inv0 = 1.0f / sum0, inv1 = 1.0f / sum1;

    uint32_t pf[8][4];
#pragma unroll
    for (int ks = 0; ks < 8; ks++) {
        __half2 t;
        t = __floats2half2_rn(sacc[2 * ks][0],     sacc[2 * ks][1]);     pf[ks][0] = *(uint32_t*)&t;
        t = __floats2half2_rn(sacc[2 * ks][2],     sacc[2 * ks][3]);     pf[ks][1] = *(uint32_t*)&t;
        t = __floats2half2_rn(sacc[2 * ks + 1][0], sacc[2 * ks + 1][1]); pf[ks][2] = *(uint32_t*)&t;
        t = __floats2half2_rn(sacc[2 * ks + 1][2], sacc[2 * ks + 1][3]); pf[ks][3] = *(uint32_t*)&t;
    }

    float oacc[16][4];
#pragma unroll
    for (int nt = 0; nt < 16; nt++)
#pragma unroll
        for (int k = 0; k < 4; k++) oacc[nt][k] = 0.f;

#pragma unroll 1
    for (int ks = 0; ks < 8; ks++) {
        const int vrow = ks * 16 + (lane & 15);
#pragma unroll
        for (int ntw = 0; ntw < 8; ntw++) {
            const int wu = ntw * 2 + (lane >> 4);
            uint32_t vv0, vv1, vv2, vv3;
            LDSM_X4_T(vv0, vv1, vv2, vv3,
                      sb + VS + (uint32_t)(vrow * 256 + ((wu ^ (vrow & 7)) << 4)));
            MMA16816(oacc[2 * ntw],     pf[ks], vv0, vv1);
            MMA16816(oacc[2 * ntw + 1], pf[ks], vv2, vv3);
        }
    }

    const int wq = 2 * (lane & 3);
    __half* ob0 = g_att + (((size_t)b * CH + c) * HH + r0) * WW;
    __half* ob1 = g_att + (((size_t)b * CH + c) * HH + r0 + 8) * WW;
#pragma unroll
    for (int nt = 0; nt < 16; nt++) {
        int w = nt * 8 + wq;
        *reinterpret_cast<__half2*>(ob0 + w) =
            __floats2half2_rn(oacc[nt][0] * inv0, oacc[nt][1] * inv0);
        *reinterpret_cast<__half2*>(ob1 + w) =
            __floats2half2_rn(oacc[nt][2] * inv1, oacc[nt][3] * inv1);
    }
}

// ---------------- proj 1x1 via fp16 mma: CTA per (b,h) row ----------------
__global__ __launch_bounds__(256, 2) void proj_mma(float* __restrict__ Y)
{
    extern __shared__ __align__(1024) char smem[];
    const uint32_t sb = smem_to_u32(smem);
    const uint32_t WS = 0, XS = 32768;
    const int bx = blockIdx.x, b = bx >> 7, h = bx & 127;
    const int tid = threadIdx.x, wid = tid >> 5, lane = tid & 31;
    const int wm = wid & 1, wn = wid >> 1;
    const int mwbase = wm * 64, nwbase = wn * 32;

#pragma unroll
    for (int j = 0; j < 16; j++) {
        int idx = tid + j * 256;
        int sec = idx >> 11;
        int rem = idx & 2047;
        int row = rem >> 4, u = rem & 15;
        const __half* src = sec
            ? (g_att + (((size_t)b * CH + row) * HH + h) * WW + u * 8)
            : (g_wpj + (size_t)row * 128 + u * 8);
        uint32_t dst = sb + (uint32_t)sec * 32768u
                     + (uint32_t)(row * 256 + ((u ^ (row & 7)) << 4));
        CP_ASYNC16(dst, src, 16);
    }
    CP_COMMIT(); CP_WAIT(0);
    __syncthreads();

    float acc[4][4][4];
#pragma unroll
    for (int i = 0; i < 4; i++)
#pragma unroll
        for (int j = 0; j < 4; j++)
#pragma unroll
            for (int k = 0; k < 4; k++) acc[i][j][k] = 0.f;

    const int q4 = lane >> 3;
    const int qr = (q4 & 1) * 8 + (lane & 7);
    const int qk = q4 >> 1;
#pragma unroll 1
    for (int ks = 0; ks < 8; ks++) {
        const int u = ks * 2 + qk;
        uint32_t ah[4][4];
#pragma unroll
        for (int mf = 0; mf < 4; mf++) {
            int rw = mwbase + mf * 16 + qr;
            LDSM_X4(ah[mf][0], ah[mf][1], ah[mf][2], ah[mf][3],
                    sb + WS + (uint32_t)(rw * 256 + ((u ^ (rw & 7)) << 4)));
        }
        const int vrow = ks * 16 + (lane & 15);
#pragma unroll
        for (int ntw = 0; ntw < 2; ntw++) {
            const int wu = (nwbase >> 3) + ntw * 2 + (lane >> 4);
            uint32_t vv0, vv1, vv2, vv3;
            LDSM_X4_T(vv0, vv1, vv2, vv3,
                      sb + XS + (uint32_t)(vrow * 256 + ((wu ^ (vrow & 7)) << 4)));
#pragma unroll
            for (int mf = 0; mf < 4; mf++) {
                MMA16816(acc[mf][ntw * 2],     ah[mf], vv0, vv1);
                MMA16816(acc[mf][ntw * 2 + 1], ah[mf], vv2, vv3);
            }
        }
    }

    const int gid = lane >> 2, tg = lane & 3;
#pragma unroll
    for (int mf = 0; mf < 4; mf++) {
        int co = mwbase + mf * 16 + gid;
        float* o0 = Y + (((size_t)b * CH + co) * HH + h) * WW;
        float* o1 = Y + (((size_t)b * CH + co + 8) * HH + h) * WW;
#pragma unroll
        for (int nf = 0; nf < 4; nf++) {
            int w = nwbase + nf * 8 + tg * 2;
            *reinterpret_cast<float2*>(o0 + w) = make_float2(acc[mf][nf][0], acc[mf][nf][1]);
            *reinterpret_cast<float2*>(o1 + w) = make_float2(acc[mf][nf][2], acc[mf][nf][3]);
        }
    }
}

// ---------------- launch ----------------
extern "C" void kernel_launch(void* const* d_in, const int* in_sizes, int n_in,
                              void* d_out, int out_size)
{
    (void)in_sizes; (void)n_in; (void)out_size;
    const float* x     = (const float*)d_in[0];
    const float* w1    = (const float*)d_in[1];
    const float* w2    = (const float*)d_in[2];
    const float* wproj = (const float*)d_in[3];
    const float* scale = (const float*)d_in[4];
    float* out = (float*)d_out;

    const int SMEM_PREP = 128 * 132 * 4;                //  67,584
    const int SMEM_CONV = 2 * 32768;                    //  65,536
    const int SMEM_ATTN = 3 * 32768 + 1024;             //  99,328
    const int SMEM_PROJ = 2 * 32768;                    //  65,536

    cudaFuncSetAttribute(prep_kernel, cudaFuncAttributeMaxDynamicSharedMemorySize, SMEM_PREP);
    cudaFuncSetAttribute(conv3x3_mma, cudaFuncAttributeMaxDynamicSharedMemorySize, SMEM_CONV);
    cudaFuncSetAttribute(attn_mma,    cudaFuncAttributeMaxDynamicSharedMemorySize, SMEM_ATTN);
    cudaFuncSetAttribute(proj_mma,    cudaFuncAttributeMaxDynamicSharedMemorySize, SMEM_PROJ);

    prep_kernel<<<567, 256, SMEM_PREP>>>(x, w1, w2, wproj);
    conv3x3_mma<<<dim3(BDIM * HH, C3 / 128), 256, SMEM_CONV>>>();
    attn_mma<<<BDIM * CH, 256, SMEM_ATTN>>>(scale);
    proj_mma<<<BDIM * HH, 256, SMEM_PROJ>>>(out);
}